// round 3
// baseline (speedup 1.0000x reference)
#include <cuda_runtime.h>
#include <math.h>

// Problem constants
#define B  32
#define C  200
#define H  56
#define W  56
#define HW 3136
#define OH 224
#define OW 224
#define KS 33
#define PAD 16

#define MSP 44          // M chunk smem pitch (floats); 176B rows, 16B aligned

// Scratch (device globals)
// g_delta layout: [hw][jj][b][e] where jj = c/2, e = c&1  (6400 floats per pixel)
__device__ float g_delta[(size_t)HW * C * B];
__device__ float g_dist[(size_t)B * HW];
__device__ float g_up[(size_t)B * OH * OW];
__device__ float g_tmp[(size_t)B * OH * OW];
__device__ float g_gw[KS];

// ---------------- packed f32x2 / async helpers ----------------
__device__ __forceinline__ unsigned long long fma2(unsigned long long a,
                                                   unsigned long long b,
                                                   unsigned long long c)
{
    unsigned long long d;
    asm("fma.rn.f32x2 %0, %1, %2, %3;" : "=l"(d) : "l"(a), "l"(b), "l"(c));
    return d;
}
__device__ __forceinline__ float2 unpack2(unsigned long long v)
{
    float2 r;
    asm("mov.b64 {%0, %1}, %2;" : "=f"(r.x), "=f"(r.y) : "l"(v));
    return r;
}
__device__ __forceinline__ unsigned int smaddr(const void* p)
{
    return (unsigned int)__cvta_generic_to_shared(p);
}
__device__ __forceinline__ void cp16(unsigned int s, const void* g)
{
    asm volatile("cp.async.cg.shared.global [%0], [%1], 16;" :: "r"(s), "l"(g));
}
#define CP_COMMIT() asm volatile("cp.async.commit_group;")
#define CP_WAIT(n)  asm volatile("cp.async.wait_group %0;" :: "n"(n))

// ---------------------------------------------------------------------------
// Kernel 1: delta prepass. emb[b][c][hw], mean[c][hw] -> g_delta[hw][jj][b][e]
// ---------------------------------------------------------------------------
__global__ void prep_delta_kernel(const float* __restrict__ emb,
                                  const float* __restrict__ mean)
{
    __shared__ float s[8][32][33];
    const int hw0 = blockIdx.x * 32;
    const int c0  = blockIdx.y * 8;
    const int lane = threadIdx.x & 31;
    const int wrp  = threadIdx.x >> 5;

    const int c = c0 + wrp;
    const float m = mean[(size_t)c * HW + hw0 + lane];
    #pragma unroll 4
    for (int b = 0; b < B; b++) {
        float e = emb[((size_t)b * C + c) * HW + hw0 + lane];
        s[wrp][b][lane] = e - m;
    }
    __syncthreads();

    const int b  = threadIdx.x & 31;
    const int cl = threadIdx.x >> 5;
    const int cc = c0 + cl;
    const int doff = (cc >> 1) * 64 + b * 2 + (cc & 1);
    #pragma unroll 4
    for (int hwl = 0; hwl < 32; hwl++) {
        g_delta[(size_t)(hw0 + hwl) * (C * B) + doff] = s[cl][b][hwl];
    }
}

// ---------------------------------------------------------------------------
// Kernel 2: per-pixel mahalanobis, j-packed f32x2 (no pack MOVs),
// cp.async double-buffered M streaming. CTA = 1 pixel, 256 thr.
// 8 tx (4 b each) x 32 ty (rows ty+32k). Rows: pass1 0..127, pass2 128..199.
// ---------------------------------------------------------------------------
__global__ void __launch_bounds__(256)
mahal_kernel(const float* __restrict__ invcov)
{
    extern __shared__ float sm[];
    float* Ds2 = sm;                           // 6400 floats [jj][b][e]
    float* Mb0 = sm + C * B;
    float* Mb1 = Mb0 + 128 * MSP;

    const int p   = blockIdx.x;
    const int tid = threadIdx.x;
    const int tx  = tid & 7;
    const int ty  = tid >> 3;
    const int b0  = tx * 4;

    const float* Mp = invcov + (size_t)p * (C * C);

    // ---- issue chunk 0 of pass 1 (rows 0..127, cols 0..39) ----
    {
        #pragma unroll
        for (int o = 0; o < 5; o++) {
            int e4 = o * 256 + tid;            // 1280 float4
            int il = e4 / 10;
            int jl = (e4 - il * 10) * 4;
            cp16(smaddr(Mb0 + il * MSP + jl), Mp + (size_t)il * C + jl);
        }
        CP_COMMIT();
    }

    // ---- load delta (overlaps with cp.async) ----
    const float* dsrc = g_delta + (size_t)p * (C * B);
    for (int i = tid * 4; i < C * B; i += 1024)
        *(float4*)&Ds2[i] = *(const float4*)&dsrc[i];

    float q0 = 0.f, q1 = 0.f, q2 = 0.f, q3 = 0.f;

    // ======================= pass 1: rows 0..127 =======================
    {
        unsigned long long acc[4][4];
        #pragma unroll
        for (int r = 0; r < 4; r++)
            #pragma unroll
            for (int w = 0; w < 4; w++) acc[r][w] = 0ull;

        #pragma unroll
        for (int ch = 0; ch < 5; ch++) {
            if (ch < 4) {
                // prefetch pass1 chunk ch+1
                float* nb = ((ch + 1) & 1) ? Mb1 : Mb0;
                const float* src = Mp + (ch + 1) * 40;
                #pragma unroll
                for (int o = 0; o < 5; o++) {
                    int e4 = o * 256 + tid;
                    int il = e4 / 10;
                    int jl = (e4 - il * 10) * 4;
                    cp16(smaddr(nb + il * MSP + jl), src + (size_t)il * C + jl);
                }
                CP_COMMIT();
            } else {
                // prefetch pass2 chunk 0 (rows 128..199, cols 0..39) into Mb1
                const float* src = Mp + (size_t)128 * C;
                #pragma unroll
                for (int o = 0; o < 3; o++) {
                    int e4 = o * 256 + tid;    // 720 float4
                    if (e4 < 720) {
                        int il = e4 / 10;
                        int jl = (e4 - il * 10) * 4;
                        cp16(smaddr(Mb1 + il * MSP + jl), src + (size_t)il * C + jl);
                    }
                }
                CP_COMMIT();
            }
            CP_WAIT(1);
            __syncthreads();

            const float* buf = (ch & 1) ? Mb1 : Mb0;
            const int jjb = ch * 20;
            #pragma unroll
            for (int u = 0; u < 10; u++) {
                ulonglong2 mA = *(const ulonglong2*)&buf[(ty      ) * MSP + u * 4];
                ulonglong2 mB = *(const ulonglong2*)&buf[(ty +  32) * MSP + u * 4];
                ulonglong2 mC = *(const ulonglong2*)&buf[(ty +  64) * MSP + u * 4];
                ulonglong2 mD = *(const ulonglong2*)&buf[(ty +  96) * MSP + u * 4];
                const float* dp = &Ds2[(jjb + u * 2) * 64 + b0 * 2];
                ulonglong2 d0 = *(const ulonglong2*)(dp);
                ulonglong2 d1 = *(const ulonglong2*)(dp + 4);
                ulonglong2 d2 = *(const ulonglong2*)(dp + 64);
                ulonglong2 d3 = *(const ulonglong2*)(dp + 68);

                acc[0][0] = fma2(mA.x, d0.x, acc[0][0]);
                acc[0][1] = fma2(mA.x, d0.y, acc[0][1]);
                acc[0][2] = fma2(mA.x, d1.x, acc[0][2]);
                acc[0][3] = fma2(mA.x, d1.y, acc[0][3]);
                acc[1][0] = fma2(mB.x, d0.x, acc[1][0]);
                acc[1][1] = fma2(mB.x, d0.y, acc[1][1]);
                acc[1][2] = fma2(mB.x, d1.x, acc[1][2]);
                acc[1][3] = fma2(mB.x, d1.y, acc[1][3]);
                acc[2][0] = fma2(mC.x, d0.x, acc[2][0]);
                acc[2][1] = fma2(mC.x, d0.y, acc[2][1]);
                acc[2][2] = fma2(mC.x, d1.x, acc[2][2]);
                acc[2][3] = fma2(mC.x, d1.y, acc[2][3]);
                acc[3][0] = fma2(mD.x, d0.x, acc[3][0]);
                acc[3][1] = fma2(mD.x, d0.y, acc[3][1]);
                acc[3][2] = fma2(mD.x, d1.x, acc[3][2]);
                acc[3][3] = fma2(mD.x, d1.y, acc[3][3]);

                acc[0][0] = fma2(mA.y, d2.x, acc[0][0]);
                acc[0][1] = fma2(mA.y, d2.y, acc[0][1]);
                acc[0][2] = fma2(mA.y, d3.x, acc[0][2]);
                acc[0][3] = fma2(mA.y, d3.y, acc[0][3]);
                acc[1][0] = fma2(mB.y, d2.x, acc[1][0]);
                acc[1][1] = fma2(mB.y, d2.y, acc[1][1]);
                acc[1][2] = fma2(mB.y, d3.x, acc[1][2]);
                acc[1][3] = fma2(mB.y, d3.y, acc[1][3]);
                acc[2][0] = fma2(mC.y, d2.x, acc[2][0]);
                acc[2][1] = fma2(mC.y, d2.y, acc[2][1]);
                acc[2][2] = fma2(mC.y, d3.x, acc[2][2]);
                acc[2][3] = fma2(mC.y, d3.y, acc[2][3]);
                acc[3][0] = fma2(mD.y, d2.x, acc[3][0]);
                acc[3][1] = fma2(mD.y, d2.y, acc[3][1]);
                acc[3][2] = fma2(mD.y, d3.x, acc[3][2]);
                acc[3][3] = fma2(mD.y, d3.y, acc[3][3]);
            }
            __syncthreads();
        }

        // fold: q_b += d_i * (even + odd)
        #pragma unroll
        for (int r = 0; r < 4; r++) {
            int i = ty + 32 * r;
            int dbase = (i >> 1) * 64 + (i & 1);
            float2 s0 = unpack2(acc[r][0]);
            float2 s1 = unpack2(acc[r][1]);
            float2 s2 = unpack2(acc[r][2]);
            float2 s3 = unpack2(acc[r][3]);
            q0 += Ds2[dbase + (b0 + 0) * 2] * (s0.x + s0.y);
            q1 += Ds2[dbase + (b0 + 1) * 2] * (s1.x + s1.y);
            q2 += Ds2[dbase + (b0 + 2) * 2] * (s2.x + s2.y);
            q3 += Ds2[dbase + (b0 + 3) * 2] * (s3.x + s3.y);
        }
    }

    // ======================= pass 2: rows 128..199 =======================
    {
        unsigned long long acc[3][4];
        #pragma unroll
        for (int r = 0; r < 3; r++)
            #pragma unroll
            for (int w = 0; w < 4; w++) acc[r][w] = 0ull;

        const float* Mp2 = Mp + (size_t)128 * C;

        #pragma unroll
        for (int ch = 0; ch < 5; ch++) {
            if (ch < 4) {
                // pass2 chunk k lives in Mb[(k+1)&1]; prefetch chunk ch+1
                float* nb = (ch & 1) ? Mb1 : Mb0;
                const float* src = Mp2 + (ch + 1) * 40;
                #pragma unroll
                for (int o = 0; o < 3; o++) {
                    int e4 = o * 256 + tid;
                    if (e4 < 720) {
                        int il = e4 / 10;
                        int jl = (e4 - il * 10) * 4;
                        cp16(smaddr(nb + il * MSP + jl), src + (size_t)il * C + jl);
                    }
                }
                CP_COMMIT();
                CP_WAIT(1);
            } else {
                CP_WAIT(0);
            }
            __syncthreads();

            const float* buf = ((ch + 1) & 1) ? Mb1 : Mb0;
            const int jjb = ch * 20;
            #pragma unroll
            for (int u = 0; u < 10; u++) {
                ulonglong2 mA = *(const ulonglong2*)&buf[(ty      ) * MSP + u * 4];
                ulonglong2 mB = *(const ulonglong2*)&buf[(ty +  32) * MSP + u * 4];
                ulonglong2 mC = *(const ulonglong2*)&buf[(ty +  64) * MSP + u * 4];
                const float* dp = &Ds2[(jjb + u * 2) * 64 + b0 * 2];
                ulonglong2 d0 = *(const ulonglong2*)(dp);
                ulonglong2 d1 = *(const ulonglong2*)(dp + 4);
                ulonglong2 d2 = *(const ulonglong2*)(dp + 64);
                ulonglong2 d3 = *(const ulonglong2*)(dp + 68);

                acc[0][0] = fma2(mA.x, d0.x, acc[0][0]);
                acc[0][1] = fma2(mA.x, d0.y, acc[0][1]);
                acc[0][2] = fma2(mA.x, d1.x, acc[0][2]);
                acc[0][3] = fma2(mA.x, d1.y, acc[0][3]);
                acc[1][0] = fma2(mB.x, d0.x, acc[1][0]);
                acc[1][1] = fma2(mB.x, d0.y, acc[1][1]);
                acc[1][2] = fma2(mB.x, d1.x, acc[1][2]);
                acc[1][3] = fma2(mB.x, d1.y, acc[1][3]);
                acc[2][0] = fma2(mC.x, d0.x, acc[2][0]);
                acc[2][1] = fma2(mC.x, d0.y, acc[2][1]);
                acc[2][2] = fma2(mC.x, d1.x, acc[2][2]);
                acc[2][3] = fma2(mC.x, d1.y, acc[2][3]);

                acc[0][0] = fma2(mA.y, d2.x, acc[0][0]);
                acc[0][1] = fma2(mA.y, d2.y, acc[0][1]);
                acc[0][2] = fma2(mA.y, d3.x, acc[0][2]);
                acc[0][3] = fma2(mA.y, d3.y, acc[0][3]);
                acc[1][0] = fma2(mB.y, d2.x, acc[1][0]);
                acc[1][1] = fma2(mB.y, d2.y, acc[1][1]);
                acc[1][2] = fma2(mB.y, d3.x, acc[1][2]);
                acc[1][3] = fma2(mB.y, d3.y, acc[1][3]);
                acc[2][0] = fma2(mC.y, d2.x, acc[2][0]);
                acc[2][1] = fma2(mC.y, d2.y, acc[2][1]);
                acc[2][2] = fma2(mC.y, d3.x, acc[2][2]);
                acc[2][3] = fma2(mC.y, d3.y, acc[2][3]);
            }
            __syncthreads();
        }

        #pragma unroll
        for (int r = 0; r < 2; r++) {
            int i = 128 + ty + 32 * r;
            int dbase = (i >> 1) * 64 + (i & 1);
            float2 s0 = unpack2(acc[r][0]);
            float2 s1 = unpack2(acc[r][1]);
            float2 s2 = unpack2(acc[r][2]);
            float2 s3 = unpack2(acc[r][3]);
            q0 += Ds2[dbase + (b0 + 0) * 2] * (s0.x + s0.y);
            q1 += Ds2[dbase + (b0 + 1) * 2] * (s1.x + s1.y);
            q2 += Ds2[dbase + (b0 + 2) * 2] * (s2.x + s2.y);
            q3 += Ds2[dbase + (b0 + 3) * 2] * (s3.x + s3.y);
        }
        if (ty < 8) {
            int i = 192 + ty;
            int dbase = (i >> 1) * 64 + (i & 1);
            float2 s0 = unpack2(acc[2][0]);
            float2 s1 = unpack2(acc[2][1]);
            float2 s2 = unpack2(acc[2][2]);
            float2 s3 = unpack2(acc[2][3]);
            q0 += Ds2[dbase + (b0 + 0) * 2] * (s0.x + s0.y);
            q1 += Ds2[dbase + (b0 + 1) * 2] * (s1.x + s1.y);
            q2 += Ds2[dbase + (b0 + 2) * 2] * (s2.x + s2.y);
            q3 += Ds2[dbase + (b0 + 3) * 2] * (s3.x + s3.y);
        }
    }

    // block reduction over ty
    __syncthreads();
    float* red = Mb0;
    red[ty * 33 + b0 + 0] = q0;
    red[ty * 33 + b0 + 1] = q1;
    red[ty * 33 + b0 + 2] = q2;
    red[ty * 33 + b0 + 3] = q3;
    __syncthreads();
    if (tid < B) {
        float acc = 0.f;
        #pragma unroll
        for (int t = 0; t < 32; t++) acc += red[t * 33 + tid];
        g_dist[(size_t)tid * HW + p] = sqrtf(fmaxf(acc, 0.f));
    }
}

// ---------------------------------------------------------------------------
// Kernel 3: gaussian weight init
// ---------------------------------------------------------------------------
__global__ void gauss_init_kernel()
{
    if (threadIdx.x == 0 && blockIdx.x == 0) {
        float w[KS];
        float s = 0.f;
        for (int i = 0; i < KS; i++) {
            float x = (float)(i - (KS - 1) / 2);
            w[i] = expf(-(x * x) / (2.f * 16.f));
            s += w[i];
        }
        for (int i = 0; i < KS; i++) g_gw[i] = w[i] / s;
    }
}

// ---------------------------------------------------------------------------
// Kernel 4: bilinear upsample 56x56 -> 224x224
// ---------------------------------------------------------------------------
__global__ void upsample_kernel()
{
    int idx = blockIdx.x * 256 + threadIdx.x;
    const int total = B * OH * OW;
    if (idx >= total) return;
    int x = idx % OW;
    int y = (idx / OW) % OH;
    int b = idx / (OW * OH);

    float sy = y * 0.25f - 0.375f;
    float sx = x * 0.25f - 0.375f;
    float fy0 = floorf(sy), fx0 = floorf(sx);
    float ay = sy - fy0, ax = sx - fx0;
    int y0 = (int)fy0, x0 = (int)fx0;
    int y1 = min(y0 + 1, H - 1);
    int x1 = min(x0 + 1, W - 1);
    y0 = max(y0, 0);
    x0 = max(x0, 0);

    const float* src = g_dist + (size_t)b * HW;
    float v00 = src[y0 * W + x0];
    float v01 = src[y0 * W + x1];
    float v10 = src[y1 * W + x0];
    float v11 = src[y1 * W + x1];
    float top = v00 + ax * (v01 - v00);
    float bot = v10 + ax * (v11 - v10);
    g_up[idx] = top + ay * (bot - top);
}

// ---------------------------------------------------------------------------
// Kernels 5/6: separable gaussian blur, reflect padding
// ---------------------------------------------------------------------------
__device__ __forceinline__ int reflect224(int i)
{
    if (i < 0) i = -i;
    if (i > OW - 1) i = 2 * (OW - 1) - i;
    return i;
}

__global__ void blur_h_kernel()
{
    __shared__ float sgw[KS];
    if (threadIdx.x < KS) sgw[threadIdx.x] = g_gw[threadIdx.x];
    __syncthreads();

    int idx = blockIdx.x * 256 + threadIdx.x;
    const int total = B * OH * OW;
    if (idx >= total) return;
    int x = idx % OW;
    int row_base = idx - x;

    float acc = 0.f;
    #pragma unroll
    for (int t = 0; t < KS; t++) {
        int xs = reflect224(x + t - PAD);
        acc += sgw[t] * g_up[row_base + xs];
    }
    g_tmp[idx] = acc;
}

__global__ void blur_v_kernel(float* __restrict__ out)
{
    __shared__ float sgw[KS];
    if (threadIdx.x < KS) sgw[threadIdx.x] = g_gw[threadIdx.x];
    __syncthreads();

    int idx = blockIdx.x * 256 + threadIdx.x;
    const int total = B * OH * OW;
    if (idx >= total) return;
    int x = idx % OW;
    int y = (idx / OW) % OH;
    int b = idx / (OW * OH);
    const float* src = g_tmp + (size_t)b * OH * OW;

    float acc = 0.f;
    #pragma unroll
    for (int t = 0; t < KS; t++) {
        int ys = reflect224(y + t - PAD);
        acc += sgw[t] * src[ys * OW + x];
    }
    out[idx] = acc;
}

// ---------------------------------------------------------------------------
// Launch
// ---------------------------------------------------------------------------
extern "C" void kernel_launch(void* const* d_in, const int* in_sizes, int n_in,
                              void* d_out, int out_size)
{
    const float* emb    = (const float*)d_in[0];
    const float* mean   = (const float*)d_in[1];
    const float* invcov = (const float*)d_in[2];
    float* out = (float*)d_out;

    const int mahal_smem = (C * B + 2 * 128 * MSP) * (int)sizeof(float);  // 70656
    cudaFuncSetAttribute(mahal_kernel,
                         cudaFuncAttributeMaxDynamicSharedMemorySize, mahal_smem);

    dim3 prep_grid(HW / 32, C / 8);
    prep_delta_kernel<<<prep_grid, 256>>>(emb, mean);

    mahal_kernel<<<HW, 256, mahal_smem>>>(invcov);

    gauss_init_kernel<<<1, 32>>>();

    const int total = B * OH * OW;
    const int nb = (total + 255) / 256;
    upsample_kernel<<<nb, 256>>>();
    blur_h_kernel<<<nb, 256>>>();
    blur_v_kernel<<<nb, 256>>>(out);
}

// round 4
// speedup vs baseline: 1.5773x; 1.5773x over previous
#include <cuda_runtime.h>
#include <math.h>

// Problem constants
#define B  32
#define C  200
#define H  56
#define W  56
#define HW 3136
#define OH 224
#define OW 224
#define KS 33
#define PAD 16

#define MSP2 68         // 64x64 chunk pitch (floats); 272B rows, 16B aligned

// Scratch (device globals) — g_delta layout: [hw][c][b]
__device__ float g_delta[(size_t)HW * C * B];
__device__ float g_dist[(size_t)B * HW];
__device__ float g_up[(size_t)B * OH * OW];
__device__ float g_tmp[(size_t)B * OH * OW];
__device__ float g_gw[KS];

// ---------------- packed f32x2 helpers ----------------
__device__ __forceinline__ unsigned long long fma2(unsigned long long a,
                                                   unsigned long long b,
                                                   unsigned long long c)
{
    unsigned long long d;
    asm("fma.rn.f32x2 %0, %1, %2, %3;" : "=l"(d) : "l"(a), "l"(b), "l"(c));
    return d;
}
__device__ __forceinline__ unsigned long long pack2(float x)
{
    unsigned long long d;
    asm("mov.b64 %0, {%1, %1};" : "=l"(d) : "f"(x));
    return d;
}
__device__ __forceinline__ float2 unpack2(unsigned long long v)
{
    float2 r;
    asm("mov.b64 {%0, %1}, %2;" : "=f"(r.x), "=f"(r.y) : "l"(v));
    return r;
}

// ---------------------------------------------------------------------------
// Kernel 1: delta transpose prepass: emb[b][c][hw] -> g_delta[hw][c][b]
// ---------------------------------------------------------------------------
__global__ void prep_delta_kernel(const float* __restrict__ emb,
                                  const float* __restrict__ mean)
{
    __shared__ float s[8][32][33];
    const int hw0 = blockIdx.x * 32;
    const int c0  = blockIdx.y * 8;
    const int lane = threadIdx.x & 31;
    const int wrp  = threadIdx.x >> 5;

    const int c = c0 + wrp;
    const float m = mean[(size_t)c * HW + hw0 + lane];
    #pragma unroll 4
    for (int b = 0; b < B; b++) {
        float e = emb[((size_t)b * C + c) * HW + hw0 + lane];
        s[wrp][b][lane] = e - m;
    }
    __syncthreads();

    const int b  = threadIdx.x & 31;
    const int cl = threadIdx.x >> 5;
    #pragma unroll 4
    for (int hwl = 0; hwl < 32; hwl++) {
        g_delta[(size_t)(hw0 + hwl) * (C * B) + (c0 + cl) * B + b] = s[cl][b][hwl];
    }
}

// ---------------------------------------------------------------------------
// Kernel 2: per-pixel mahalanobis exploiting SYMMETRY of M.
// q = sum over 64x64 blocks: diag blocks weight 1, lower blocks weight 2,
// plus 8-row border strip (rows 192..199) with col-weight 2 (j<192) / 1.
// CTA = 1 pixel, 256 thr = 8 tx (4 b) x 32 ty (rows ty, ty+32 of block).
// ---------------------------------------------------------------------------
__global__ void __launch_bounds__(256)
mahal_kernel(const float* __restrict__ invcov)
{
    extern __shared__ float sm[];
    float* Ds  = sm;                      // 6400 floats [j][b]
    float* Mb0 = sm + C * B;              // 64*68 = 4352
    float* Mb1 = Mb0 + 64 * MSP2;         // 4352  (also border staging)

    const int p   = blockIdx.x;
    const int tid = threadIdx.x;
    const int tx  = tid & 7;
    const int ty  = tid >> 3;
    const int b0  = tx * 4;

    const float* Mp = invcov + (size_t)p * (C * C);

    // chunk schedule: (I,J,weight); I,J are 64-blocks, J <= I
    const int   CI[6] = {0, 1, 1, 2, 2, 2};
    const int   CJ[6] = {0, 0, 1, 0, 1, 2};
    const float CW[6] = {1.f, 2.f, 1.f, 2.f, 2.f, 1.f};

    // ---- issue chunk 0 LDGs first (latency hidden behind staging+border) ----
    float4 st[4];
    #pragma unroll
    for (int o = 0; o < 4; o++) {
        int e4 = o * 256 + tid;            // 1024 float4 = 64 rows x 16
        int il = e4 >> 4;
        int jl = (e4 & 15) * 4;
        st[o] = *(const float4*)&Mp[(size_t)il * C + jl];   // (I=0,J=0)
    }

    // ---- stage delta (coalesced) ----
    const float* dsrc = g_delta + (size_t)p * (C * B);
    for (int i = tid * 4; i < C * B; i += 1024)
        *(float4*)&Ds[i] = *(const float4*)&dsrc[i];

    // ---- stage border rows 192..199 (8 x 200 floats) into Mb1 ----
    for (int i = tid * 4; i < 8 * C; i += 1024)
        *(float4*)&Mb1[i] = *(const float4*)&Mp[(size_t)192 * C + i];

    __syncthreads();

    float q0 = 0.f, q1 = 0.f, q2 = 0.f, q3 = 0.f;

    // ---- border strip: q += d_i * sum_j w_j M_ij d_j, rows i=192..199 ----
    #pragma unroll
    for (int rr = 0; rr < 8; rr++) {
        const float* mrow = &Mb1[rr * C];
        float p0 = 0.f, p1 = 0.f, p2 = 0.f, p3 = 0.f;
        #pragma unroll
        for (int s = 0; s < 7; s++) {
            int j = ty + 32 * s;
            if (j < C) {
                float wm = mrow[j] * ((j < 192) ? 2.f : 1.f);
                float4 dj = *(const float4*)&Ds[j * B + b0];
                p0 += wm * dj.x; p1 += wm * dj.y;
                p2 += wm * dj.z; p3 += wm * dj.w;
            }
        }
        float4 di = *(const float4*)&Ds[(192 + rr) * B + b0];
        q0 += di.x * p0; q1 += di.y * p1; q2 += di.z * p2; q3 += di.w * p3;
    }

    // ---- 6-chunk pipeline over 64x64 blocks, register-staged double buffer ----
    #pragma unroll
    for (int k = 0; k < 6; k++) {
        float* buf = (k & 1) ? Mb1 : Mb0;
        __syncthreads();                       // prior readers of buf done
        #pragma unroll
        for (int o = 0; o < 4; o++) {
            int e4 = o * 256 + tid;
            int il = e4 >> 4;
            int jl = (e4 & 15) * 4;
            *(float4*)&buf[il * MSP2 + jl] = st[o];
        }
        __syncthreads();

        if (k < 5) {                           // prefetch next chunk
            const float* src = Mp + (size_t)(64 * CI[k + 1]) * C + 64 * CJ[k + 1];
            #pragma unroll
            for (int o = 0; o < 4; o++) {
                int e4 = o * 256 + tid;
                int il = e4 >> 4;
                int jl = (e4 & 15) * 4;
                st[o] = *(const float4*)&src[(size_t)il * C + jl];
            }
        }

        // compute chunk k
        unsigned long long a00 = 0ull, a01 = 0ull, a10 = 0ull, a11 = 0ull;
        const float* m0p = &buf[ty * MSP2];
        const float* m1p = &buf[(ty + 32) * MSP2];
        const float* dbase = &Ds[(64 * CJ[k]) * B + b0];
        #pragma unroll
        for (int u = 0; u < 16; u++) {
            float4 mv0 = *(const float4*)(m0p + u * 4);
            float4 mv1 = *(const float4*)(m1p + u * 4);
            #pragma unroll
            for (int jj = 0; jj < 4; jj++) {
                ulonglong2 du = *(const ulonglong2*)(dbase + (u * 4 + jj) * B);
                float c0 = (jj == 0) ? mv0.x : (jj == 1) ? mv0.y : (jj == 2) ? mv0.z : mv0.w;
                float c1 = (jj == 0) ? mv1.x : (jj == 1) ? mv1.y : (jj == 2) ? mv1.z : mv1.w;
                unsigned long long m0 = pack2(c0);
                a00 = fma2(m0, du.x, a00);
                a01 = fma2(m0, du.y, a01);
                unsigned long long m1 = pack2(c1);
                a10 = fma2(m1, du.x, a10);
                a11 = fma2(m1, du.y, a11);
            }
        }

        // fold with weight
        {
            const float w = CW[k];
            const int i0 = 64 * CI[k] + ty;
            const int i1 = i0 + 32;
            float4 dv0 = *(const float4*)&Ds[i0 * B + b0];
            float4 dv1 = *(const float4*)&Ds[i1 * B + b0];
            float2 s00 = unpack2(a00), s01 = unpack2(a01);
            float2 s10 = unpack2(a10), s11 = unpack2(a11);
            q0 += w * (dv0.x * s00.x + dv1.x * s10.x);
            q1 += w * (dv0.y * s00.y + dv1.y * s10.y);
            q2 += w * (dv0.z * s01.x + dv1.z * s11.x);
            q3 += w * (dv0.w * s01.y + dv1.w * s11.y);
        }
    }

    // ---- block reduction over ty ----
    __syncthreads();
    float* red = Mb0;                   // 32*33 floats scratch
    red[ty * 33 + b0 + 0] = q0;
    red[ty * 33 + b0 + 1] = q1;
    red[ty * 33 + b0 + 2] = q2;
    red[ty * 33 + b0 + 3] = q3;
    __syncthreads();
    if (tid < B) {
        float acc = 0.f;
        #pragma unroll
        for (int t = 0; t < 32; t++) acc += red[t * 33 + tid];
        g_dist[(size_t)tid * HW + p] = sqrtf(fmaxf(acc, 0.f));
    }
}

// ---------------------------------------------------------------------------
// Kernel 3: gaussian weight init
// ---------------------------------------------------------------------------
__global__ void gauss_init_kernel()
{
    if (threadIdx.x == 0 && blockIdx.x == 0) {
        float w[KS];
        float s = 0.f;
        for (int i = 0; i < KS; i++) {
            float x = (float)(i - (KS - 1) / 2);
            w[i] = expf(-(x * x) / (2.f * 16.f));
            s += w[i];
        }
        for (int i = 0; i < KS; i++) g_gw[i] = w[i] / s;
    }
}

// ---------------------------------------------------------------------------
// Kernel 4: bilinear upsample 56x56 -> 224x224
// ---------------------------------------------------------------------------
__global__ void upsample_kernel()
{
    int idx = blockIdx.x * 256 + threadIdx.x;
    const int total = B * OH * OW;
    if (idx >= total) return;
    int x = idx % OW;
    int y = (idx / OW) % OH;
    int b = idx / (OW * OH);

    float sy = y * 0.25f - 0.375f;
    float sx = x * 0.25f - 0.375f;
    float fy0 = floorf(sy), fx0 = floorf(sx);
    float ay = sy - fy0, ax = sx - fx0;
    int y0 = (int)fy0, x0 = (int)fx0;
    int y1 = min(y0 + 1, H - 1);
    int x1 = min(x0 + 1, W - 1);
    y0 = max(y0, 0);
    x0 = max(x0, 0);

    const float* src = g_dist + (size_t)b * HW;
    float v00 = src[y0 * W + x0];
    float v01 = src[y0 * W + x1];
    float v10 = src[y1 * W + x0];
    float v11 = src[y1 * W + x1];
    float top = v00 + ax * (v01 - v00);
    float bot = v10 + ax * (v11 - v10);
    g_up[idx] = top + ay * (bot - top);
}

// ---------------------------------------------------------------------------
// Kernels 5/6: separable gaussian blur, reflect padding
// ---------------------------------------------------------------------------
__device__ __forceinline__ int reflect224(int i)
{
    if (i < 0) i = -i;
    if (i > OW - 1) i = 2 * (OW - 1) - i;
    return i;
}

__global__ void blur_h_kernel()
{
    __shared__ float sgw[KS];
    if (threadIdx.x < KS) sgw[threadIdx.x] = g_gw[threadIdx.x];
    __syncthreads();

    int idx = blockIdx.x * 256 + threadIdx.x;
    const int total = B * OH * OW;
    if (idx >= total) return;
    int x = idx % OW;
    int row_base = idx - x;

    float acc = 0.f;
    #pragma unroll
    for (int t = 0; t < KS; t++) {
        int xs = reflect224(x + t - PAD);
        acc += sgw[t] * g_up[row_base + xs];
    }
    g_tmp[idx] = acc;
}

__global__ void blur_v_kernel(float* __restrict__ out)
{
    __shared__ float sgw[KS];
    if (threadIdx.x < KS) sgw[threadIdx.x] = g_gw[threadIdx.x];
    __syncthreads();

    int idx = blockIdx.x * 256 + threadIdx.x;
    const int total = B * OH * OW;
    if (idx >= total) return;
    int x = idx % OW;
    int y = (idx / OW) % OH;
    int b = idx / (OW * OH);
    const float* src = g_tmp + (size_t)b * OH * OW;

    float acc = 0.f;
    #pragma unroll
    for (int t = 0; t < KS; t++) {
        int ys = reflect224(y + t - PAD);
        acc += sgw[t] * src[ys * OW + x];
    }
    out[idx] = acc;
}

// ---------------------------------------------------------------------------
// Launch
// ---------------------------------------------------------------------------
extern "C" void kernel_launch(void* const* d_in, const int* in_sizes, int n_in,
                              void* d_out, int out_size)
{
    const float* emb    = (const float*)d_in[0];
    const float* mean   = (const float*)d_in[1];
    const float* invcov = (const float*)d_in[2];
    float* out = (float*)d_out;

    const int mahal_smem = (C * B + 2 * 64 * MSP2) * (int)sizeof(float);  // 60416
    cudaFuncSetAttribute(mahal_kernel,
                         cudaFuncAttributeMaxDynamicSharedMemorySize, mahal_smem);

    dim3 prep_grid(HW / 32, C / 8);
    prep_delta_kernel<<<prep_grid, 256>>>(emb, mean);

    mahal_kernel<<<HW, 256, mahal_smem>>>(invcov);

    gauss_init_kernel<<<1, 32>>>();

    const int total = B * OH * OW;
    const int nb = (total + 255) / 256;
    upsample_kernel<<<nb, 256>>>();
    blur_h_kernel<<<nb, 256>>>();
    blur_v_kernel<<<nb, 256>>>(out);
}